// round 3
// baseline (speedup 1.0000x reference)
#include <cuda_runtime.h>
#include <float.h>

#define N_NODES 100000
#define N_EDGES 1200000
#define IN_F 128
#define HID 64
#define OUT_F 40

// ---------------- device scratch (no allocations allowed) ----------------
__device__ int   g_deg[N_NODES];          // in-degree incl. self-loop
__device__ float g_dinv[N_NODES];
__device__ int   g_rowptr[N_NODES + 1];   // CSR row pointers (real edges only)
__device__ int   g_cur[N_NODES];          // fill cursors
__device__ int   g_csr[N_EDGES];          // src node per CSR slot
__device__ int   g_edge[2 * N_EDGES];     // int32 [src | dst]
__device__ int   g_is64;
__device__ float g_hs[(size_t)N_NODES * HID];    // dinv-scaled transformed feats
__device__ float g_h1[(size_t)N_NODES * HID];    // layer-1 activations

// ---------------- edge dtype detect ----------------
__global__ void k_detect(const long long* __restrict__ ei, int n) {
    if (threadIdx.x == 0 && blockIdx.x == 0) {
        int ok = 1;
        #pragma unroll
        for (int i = 0; i < 16; i++) {
            long long v = ei[i];
            if (v < 0 || v >= n) ok = 0;
        }
        g_is64 = ok;
    }
}

__global__ void k_deg_init(int n) {
    int i = blockIdx.x * blockDim.x + threadIdx.x;
    if (i < n) g_deg[i] = 1;  // self-loop
}

// convert + count in-degree of dst half in one pass
__global__ void k_convert(const void* __restrict__ ei, int e) {
    int i = blockIdx.x * blockDim.x + threadIdx.x;
    if (i < 2 * e) {
        int v = g_is64 ? (int)((const long long*)ei)[i]
                       : ((const int*)ei)[i];
        g_edge[i] = v;
        if (i >= e) atomicAdd(&g_deg[v], 1);
    }
}

__global__ void k_dinv(int n) {
    int i = blockIdx.x * blockDim.x + threadIdx.x;
    if (i < n) g_dinv[i] = rsqrtf((float)g_deg[i]);
}

// single-block exclusive scan over (deg-1) -> rowptr, cur
__global__ void k_scan(int n) {
    __shared__ int warpsum[32];
    __shared__ int s_carry;
    const int tid = threadIdx.x, lane = tid & 31, wid = tid >> 5;
    if (tid == 0) s_carry = 0;
    __syncthreads();

    for (int base = 0; base < n; base += 1024) {
        int i = base + tid;
        int v = (i < n) ? (g_deg[i] - 1) : 0;
        int incl = v;
        #pragma unroll
        for (int off = 1; off < 32; off <<= 1) {
            int t = __shfl_up_sync(0xffffffffu, incl, off);
            if (lane >= off) incl += t;
        }
        if (lane == 31) warpsum[wid] = incl;
        __syncthreads();
        if (wid == 0) {
            int ws = warpsum[lane];
            int wincl = ws;
            #pragma unroll
            for (int off = 1; off < 32; off <<= 1) {
                int t = __shfl_up_sync(0xffffffffu, wincl, off);
                if (lane >= off) wincl += t;
            }
            warpsum[lane] = wincl - ws;  // exclusive warp offsets
        }
        __syncthreads();
        int excl = s_carry + warpsum[wid] + (incl - v);
        if (i < n) { g_rowptr[i] = excl; g_cur[i] = excl; }
        __syncthreads();
        if (tid == 1023) s_carry += warpsum[31] + incl;
        __syncthreads();
    }
    if (tid == 0) g_rowptr[n] = s_carry;
}

__global__ void k_fill(int e) {
    int i = blockIdx.x * blockDim.x + threadIdx.x;
    if (i < e) {
        int s = g_edge[i];
        int d = g_edge[e + i];
        int pos = atomicAdd(&g_cur[d], 1);
        g_csr[pos] = s;
    }
}

// ------- dense GEMM: g_hs[n,64] = (A[n,K] @ W[K,64]) * dinv[row] -------
// 128-row x 64-col tile per 128-thread block, 8x8 micro-tiles,
// A staged transposed (k-major) in smem so inner loop is 4x LDS.128 / 64 FFMA.
template <int K>
__global__ void __launch_bounds__(128) k_gemm_hs(const float* __restrict__ A,
                                                 const float* __restrict__ W, int n) {
    const int KP = 32;
    __shared__ float sAT[KP][136];  // [k][row], padded
    __shared__ float sW[KP][64];    // [k][col]

    const int t = threadIdx.x;      // 128 threads
    const int row0 = blockIdx.x * 128;
    const int tr = t >> 3, tc = t & 7;   // 16 x 8 thread grid
    const int r0 = tr * 8, c0 = tc * 8;

    float acc[8][8] = {};

    for (int k0 = 0; k0 < K; k0 += KP) {
        __syncthreads();
        // A: thread t loads its whole row slice (row0+t, k0..k0+31), stores transposed
        {
            int r = row0 + t;
            float4 v[8];
            if (r < n) {
                const float4* src = (const float4*)(A + (size_t)r * K + k0);
                #pragma unroll
                for (int i = 0; i < 8; i++) v[i] = src[i];
            } else {
                #pragma unroll
                for (int i = 0; i < 8; i++) v[i] = make_float4(0.f, 0.f, 0.f, 0.f);
            }
            #pragma unroll
            for (int i = 0; i < 8; i++) {
                sAT[4 * i + 0][t] = v[i].x;
                sAT[4 * i + 1][t] = v[i].y;
                sAT[4 * i + 2][t] = v[i].z;
                sAT[4 * i + 3][t] = v[i].w;
            }
        }
        // W: KP x 64 floats = 512 float4, 4 per thread (layout matches, direct copy)
        {
            const float4* wsrc = (const float4*)(W + (size_t)k0 * 64);
            #pragma unroll
            for (int i = 0; i < 4; i++) {
                int idx = t + i * 128;      // 0..511
                int kk = idx >> 4;
                int cc = idx & 15;
                ((float4*)&sW[kk][0])[cc] = wsrc[idx];
            }
        }
        __syncthreads();

        #pragma unroll
        for (int kk = 0; kk < KP; kk++) {
            float a[8], w[8];
            *(float4*)&a[0] = *(float4*)&sAT[kk][r0];
            *(float4*)&a[4] = *(float4*)&sAT[kk][r0 + 4];
            *(float4*)&w[0] = *(float4*)&sW[kk][c0];
            *(float4*)&w[4] = *(float4*)&sW[kk][c0 + 4];
            #pragma unroll
            for (int i = 0; i < 8; i++)
                #pragma unroll
                for (int j = 0; j < 8; j++)
                    acc[i][j] += a[i] * w[j];
        }
    }

    #pragma unroll
    for (int i = 0; i < 8; i++) {
        int r = row0 + r0 + i;
        if (r < n) {
            float dv = g_dinv[r];
            *(float4*)&g_hs[(size_t)r * 64 + c0] =
                make_float4(acc[i][0] * dv, acc[i][1] * dv, acc[i][2] * dv, acc[i][3] * dv);
            *(float4*)&g_hs[(size_t)r * 64 + c0 + 4] =
                make_float4(acc[i][4] * dv, acc[i][5] * dv, acc[i][6] * dv, acc[i][7] * dv);
        }
    }
}

// ---- aggregation: out[v] = act(dinv[v]*(hs[v] + sum_{dst=v} hs[src]) + b)
// one warp per node; lane owns a float2 (feats 2*lane, 2*lane+1).
// csr indices batch-loaded coalesced, shfl-broadcast; 4-deep load unroll.
__global__ void k_agg(const float* __restrict__ b, float* __restrict__ out,
                      int n, int do_relu) {
    int gw = (blockIdx.x * blockDim.x + threadIdx.x) >> 5;
    int lane = threadIdx.x & 31;
    if (gw >= n) return;

    int beg = g_rowptr[gw], end = g_rowptr[gw + 1];
    float2 a = *(const float2*)(g_hs + (size_t)gw * 64 + 2 * lane);

    for (int base = beg; base < end; base += 32) {
        int cnt = min(32, end - base);
        int idx = (lane < cnt) ? g_csr[base + lane] : 0;
        int i = 0;
        for (; i + 4 <= cnt; i += 4) {
            int s0 = __shfl_sync(0xffffffffu, idx, i);
            int s1 = __shfl_sync(0xffffffffu, idx, i + 1);
            int s2 = __shfl_sync(0xffffffffu, idx, i + 2);
            int s3 = __shfl_sync(0xffffffffu, idx, i + 3);
            float2 v0 = *(const float2*)(g_hs + (size_t)s0 * 64 + 2 * lane);
            float2 v1 = *(const float2*)(g_hs + (size_t)s1 * 64 + 2 * lane);
            float2 v2 = *(const float2*)(g_hs + (size_t)s2 * 64 + 2 * lane);
            float2 v3 = *(const float2*)(g_hs + (size_t)s3 * 64 + 2 * lane);
            a.x += (v0.x + v1.x) + (v2.x + v3.x);
            a.y += (v0.y + v1.y) + (v2.y + v3.y);
        }
        for (; i < cnt; i++) {
            int s = __shfl_sync(0xffffffffu, idx, i);
            float2 v = *(const float2*)(g_hs + (size_t)s * 64 + 2 * lane);
            a.x += v.x;
            a.y += v.y;
        }
    }

    float dv = g_dinv[gw];
    float vx = a.x * dv + b[2 * lane];
    float vy = a.y * dv + b[2 * lane + 1];
    if (do_relu) { vx = fmaxf(vx, 0.f); vy = fmaxf(vy, 0.f); }
    *(float2*)(out + (size_t)gw * 64 + 2 * lane) = make_float2(vx, vy);
}

// ------------- head: logits = emb @ Wc + bc, softmax, argmax -------------
// one warp per node, 16 nodes per 512-thread block; emb in registers + shfl.
__global__ void k_head(const float* __restrict__ emb, const float* __restrict__ Wc,
                       const float* __restrict__ bc, float* __restrict__ logits,
                       float* __restrict__ soft, float* __restrict__ hard, int n) {
    __shared__ float sW[64 * OUT_F];
    __shared__ float sb[OUT_F];

    int t = threadIdx.x;
    for (int i = t; i < 64 * OUT_F; i += 512) sW[i] = Wc[i];
    if (t < OUT_F) sb[t] = bc[t];
    __syncthreads();

    int w = t >> 5, lane = t & 31;
    int node = blockIdx.x * 16 + w;
    if (node >= n) return;

    float e0 = emb[(size_t)node * 64 + lane];
    float e1 = emb[(size_t)node * 64 + lane + 32];

    float acc0 = sb[lane];
    float acc1 = (lane < 8) ? sb[lane + 32] : 0.f;
    #pragma unroll
    for (int k = 0; k < 32; k++) {
        float e = __shfl_sync(0xffffffffu, e0, k);
        acc0 += e * sW[k * OUT_F + lane];
        if (lane < 8) acc1 += e * sW[k * OUT_F + lane + 32];
    }
    #pragma unroll
    for (int k = 0; k < 32; k++) {
        float e = __shfl_sync(0xffffffffu, e1, k);
        acc0 += e * sW[(k + 32) * OUT_F + lane];
        if (lane < 8) acc1 += e * sW[(k + 32) * OUT_F + lane + 32];
    }

    logits[(size_t)node * OUT_F + lane] = acc0;
    if (lane < 8) logits[(size_t)node * OUT_F + lane + 32] = acc1;

    float m = fmaxf(acc0, (lane < 8) ? acc1 : -FLT_MAX);
    #pragma unroll
    for (int o = 16; o > 0; o >>= 1) m = fmaxf(m, __shfl_xor_sync(0xffffffffu, m, o));
    float ex0 = __expf(acc0 - m);
    float ex1 = (lane < 8) ? __expf(acc1 - m) : 0.f;
    float s = ex0 + ex1;
    #pragma unroll
    for (int o = 16; o > 0; o >>= 1) s += __shfl_xor_sync(0xffffffffu, s, o);
    float inv = 1.f / s;
    soft[(size_t)node * OUT_F + lane] = ex0 * inv;
    if (lane < 8) soft[(size_t)node * OUT_F + lane + 32] = ex1 * inv;

    int cand = 0x7fffffff;
    if (acc0 == m) cand = lane;
    if (lane < 8 && acc1 == m) cand = min(cand, lane + 32);
    #pragma unroll
    for (int o = 16; o > 0; o >>= 1) cand = min(cand, __shfl_xor_sync(0xffffffffu, cand, o));
    if (lane == 0) hard[node] = (float)cand;
}

extern "C" void kernel_launch(void* const* d_in, const int* in_sizes, int n_in,
                              void* d_out, int out_size) {
    const float* x  = (const float*)d_in[0];
    const void*  ei = d_in[1];
    const float* W1 = (const float*)d_in[2];
    const float* b1 = (const float*)d_in[3];
    const float* W2 = (const float*)d_in[4];
    const float* b2 = (const float*)d_in[5];
    const float* Wc = (const float*)d_in[6];
    const float* bc = (const float*)d_in[7];

    const int N = in_sizes[0] / IN_F;
    const int E = in_sizes[1] / 2;

    float* outp   = (float*)d_out;
    float* logits = outp;
    float* emb    = outp + (size_t)N * OUT_F;
    float* soft   = emb  + (size_t)N * HID;
    float* hard   = soft + (size_t)N * OUT_F;

    const int TB = 256;

    // CSR build (int atomics only)
    k_detect<<<1, 32>>>((const long long*)ei, N);
    k_deg_init<<<(N + TB - 1) / TB, TB>>>(N);
    k_convert<<<(2 * E + TB - 1) / TB, TB>>>(ei, E);
    k_dinv<<<(N + TB - 1) / TB, TB>>>(N);
    k_scan<<<1, 1024>>>(N);
    k_fill<<<(E + TB - 1) / TB, TB>>>(E);

    // layer 1: g_hs = (x@W1)*dinv ; g_h1 = relu(agg + b1)
    k_gemm_hs<IN_F><<<(N + 127) / 128, 128>>>(x, W1, N);
    k_agg<<<((N * 32) + TB - 1) / TB, TB>>>(b1, g_h1, N, 1);

    // layer 2: g_hs = (g_h1@W2)*dinv ; emb = agg + b2
    k_gemm_hs<HID><<<(N + 127) / 128, 128>>>(g_h1, W2, N);
    k_agg<<<((N * 32) + TB - 1) / TB, TB>>>(b2, emb, N, 0);

    // head
    k_head<<<(N + 15) / 16, 512>>>(emb, Wc, bc, logits, soft, hard, N);
}

// round 4
// speedup vs baseline: 1.1856x; 1.1856x over previous
#include <cuda_runtime.h>
#include <float.h>

#define N_NODES 100000
#define N_EDGES 1200000
#define IN_F 128
#define HID 64
#define OUT_F 40

// ---------------- device scratch (no allocations allowed) ----------------
__device__ int   g_deg[N_NODES];          // in-degree incl. self-loop
__device__ float g_dinv[N_NODES];
__device__ int   g_rowptr[N_NODES + 1];   // CSR row pointers (real edges only)
__device__ int   g_cur[N_NODES];          // fill cursors
__device__ int   g_csr[N_EDGES];          // src node per CSR slot
__device__ int   g_edge[2 * N_EDGES];     // int32 [src | dst]
__device__ int   g_is64;
__device__ float g_hs[(size_t)N_NODES * HID];    // transformed feats (UNscaled)
__device__ float g_h1[(size_t)N_NODES * HID];    // layer-1 activations

// ---------------- edge dtype detect ----------------
__global__ void k_detect(const long long* __restrict__ ei, int n) {
    if (threadIdx.x == 0 && blockIdx.x == 0) {
        int ok = 1;
        #pragma unroll
        for (int i = 0; i < 16; i++) {
            long long v = ei[i];
            if (v < 0 || v >= n) ok = 0;
        }
        g_is64 = ok;
    }
}

__global__ void k_deg_init(int n) {
    int i = blockIdx.x * blockDim.x + threadIdx.x;
    if (i < n) g_deg[i] = 1;  // self-loop
}

// convert + count in-degree of dst half in one pass
__global__ void k_convert(const void* __restrict__ ei, int e) {
    int i = blockIdx.x * blockDim.x + threadIdx.x;
    if (i < 2 * e) {
        int v = g_is64 ? (int)((const long long*)ei)[i]
                       : ((const int*)ei)[i];
        g_edge[i] = v;
        if (i >= e) atomicAdd(&g_deg[v], 1);
    }
}

__global__ void k_dinv(int n) {
    int i = blockIdx.x * blockDim.x + threadIdx.x;
    if (i < n) g_dinv[i] = rsqrtf((float)g_deg[i]);
}

// single-block exclusive scan over (deg-1) -> rowptr, cur
__global__ void k_scan(int n) {
    __shared__ int warpsum[32];
    __shared__ int s_carry;
    const int tid = threadIdx.x, lane = tid & 31, wid = tid >> 5;
    if (tid == 0) s_carry = 0;
    __syncthreads();

    for (int base = 0; base < n; base += 1024) {
        int i = base + tid;
        int v = (i < n) ? (g_deg[i] - 1) : 0;
        int incl = v;
        #pragma unroll
        for (int off = 1; off < 32; off <<= 1) {
            int t = __shfl_up_sync(0xffffffffu, incl, off);
            if (lane >= off) incl += t;
        }
        if (lane == 31) warpsum[wid] = incl;
        __syncthreads();
        if (wid == 0) {
            int ws = warpsum[lane];
            int wincl = ws;
            #pragma unroll
            for (int off = 1; off < 32; off <<= 1) {
                int t = __shfl_up_sync(0xffffffffu, wincl, off);
                if (lane >= off) wincl += t;
            }
            warpsum[lane] = wincl - ws;  // exclusive warp offsets
        }
        __syncthreads();
        int excl = s_carry + warpsum[wid] + (incl - v);
        if (i < n) { g_rowptr[i] = excl; g_cur[i] = excl; }
        __syncthreads();
        if (tid == 1023) s_carry += warpsum[31] + incl;
        __syncthreads();
    }
    if (tid == 0) g_rowptr[n] = s_carry;
}

__global__ void k_fill(int e) {
    int i = blockIdx.x * blockDim.x + threadIdx.x;
    if (i < e) {
        int s = g_edge[i];
        int d = g_edge[e + i];
        int pos = atomicAdd(&g_cur[d], 1);
        g_csr[pos] = s;
    }
}

// ------- dense GEMM: g_hs[n,64] = A[n,K] @ W[K,64]  (no dinv scaling) -------
// 64x64 tile per 256-thread block, 4x4 register blocking (R2-proven shape).
template <int K>
__global__ void k_gemm_hs(const float* __restrict__ A, const float* __restrict__ W, int n) {
    __shared__ __align__(16) float sW[64 * 64];
    __shared__ float sA[64 * 65];

    const int t = threadIdx.x;           // 256 threads
    const int row0 = blockIdx.x * 64;
    const int ty = t >> 4, tx = t & 15;  // 16x16 thread tile
    const int r0 = ty * 4, c0 = tx * 4;

    float acc[4][4] = {};

    for (int k0 = 0; k0 < K; k0 += 64) {
        __syncthreads();
        for (int i = t; i < 64 * 64 / 4; i += 256)
            ((float4*)sW)[i] = ((const float4*)(W + (size_t)k0 * 64))[i];
        for (int i = t; i < 64 * 16; i += 256) {
            int r = i >> 4;
            int kc = (i & 15) * 4;
            float4 v = make_float4(0.f, 0.f, 0.f, 0.f);
            if (row0 + r < n)
                v = *(const float4*)(A + (size_t)(row0 + r) * K + k0 + kc);
            float* d = &sA[r * 65 + kc];
            d[0] = v.x; d[1] = v.y; d[2] = v.z; d[3] = v.w;
        }
        __syncthreads();

        #pragma unroll 8
        for (int kk = 0; kk < 64; kk++) {
            float4 w4 = *(float4*)&sW[kk * 64 + c0];
            #pragma unroll
            for (int j = 0; j < 4; j++) {
                float a = sA[(r0 + j) * 65 + kk];
                acc[j][0] += a * w4.x;
                acc[j][1] += a * w4.y;
                acc[j][2] += a * w4.z;
                acc[j][3] += a * w4.w;
            }
        }
    }

    #pragma unroll
    for (int j = 0; j < 4; j++) {
        int r = row0 + r0 + j;
        if (r < n)
            *(float4*)&g_hs[(size_t)r * 64 + c0] =
                make_float4(acc[j][0], acc[j][1], acc[j][2], acc[j][3]);
    }
}

// agg: out[v] = act(dinv[v]*(dinv[v]*hs[v] + sum_{dst=v} dinv[s]*hs[s]) + b)
// one warp per node; lane owns float2 (feats 2*lane, 2*lane+1).
// uniform (broadcast) index loads, unroll 4 for MLP.
__global__ void k_agg(const float* __restrict__ b, float* __restrict__ out,
                      int n, int do_relu) {
    int gw = (blockIdx.x * blockDim.x + threadIdx.x) >> 5;
    int lane = threadIdx.x & 31;
    if (gw >= n) return;

    int beg = g_rowptr[gw], end = g_rowptr[gw + 1];
    float dv = g_dinv[gw];
    float2 hv = *(const float2*)(g_hs + (size_t)gw * 64 + 2 * lane);
    float ax = dv * hv.x;
    float ay = dv * hv.y;

    int j = beg;
    for (; j + 4 <= end; j += 4) {
        int s0 = g_csr[j];
        int s1 = g_csr[j + 1];
        int s2 = g_csr[j + 2];
        int s3 = g_csr[j + 3];
        float d0 = g_dinv[s0];
        float d1 = g_dinv[s1];
        float d2 = g_dinv[s2];
        float d3 = g_dinv[s3];
        float2 v0 = *(const float2*)(g_hs + (size_t)s0 * 64 + 2 * lane);
        float2 v1 = *(const float2*)(g_hs + (size_t)s1 * 64 + 2 * lane);
        float2 v2 = *(const float2*)(g_hs + (size_t)s2 * 64 + 2 * lane);
        float2 v3 = *(const float2*)(g_hs + (size_t)s3 * 64 + 2 * lane);
        ax += d0 * v0.x + d1 * v1.x + d2 * v2.x + d3 * v3.x;
        ay += d0 * v0.y + d1 * v1.y + d2 * v2.y + d3 * v3.y;
    }
    for (; j < end; j++) {
        int s = g_csr[j];
        float d = g_dinv[s];
        float2 v = *(const float2*)(g_hs + (size_t)s * 64 + 2 * lane);
        ax += d * v.x;
        ay += d * v.y;
    }

    float vx = ax * dv + b[2 * lane];
    float vy = ay * dv + b[2 * lane + 1];
    if (do_relu) { vx = fmaxf(vx, 0.f); vy = fmaxf(vy, 0.f); }
    *(float2*)(out + (size_t)gw * 64 + 2 * lane) = make_float2(vx, vy);
}

// ------------- head: logits = emb @ Wc + bc, softmax, argmax -------------
// one warp per node, 8 nodes per 256-thread block (R2-proven shape).
__global__ void k_head(const float* __restrict__ emb, const float* __restrict__ Wc,
                       const float* __restrict__ bc, float* __restrict__ logits,
                       float* __restrict__ soft, float* __restrict__ hard, int n) {
    __shared__ float sW[64 * OUT_F];
    __shared__ float sb[OUT_F];
    __shared__ float sE[8][64];

    int t = threadIdx.x;
    for (int i = t; i < 64 * OUT_F; i += 256) sW[i] = Wc[i];
    if (t < OUT_F) sb[t] = bc[t];

    int w = t >> 5, lane = t & 31;
    int node = blockIdx.x * 8 + w;
    if (node < n) {
        sE[w][lane]      = emb[(size_t)node * 64 + lane];
        sE[w][lane + 32] = emb[(size_t)node * 64 + lane + 32];
    }
    __syncthreads();
    if (node >= n) return;

    float acc0 = sb[lane];
    float acc1 = (lane < 8) ? sb[lane + 32] : 0.f;
    #pragma unroll 8
    for (int k = 0; k < 64; k++) {
        float e = sE[w][k];
        acc0 += e * sW[k * OUT_F + lane];
        if (lane < 8) acc1 += e * sW[k * OUT_F + lane + 32];
    }

    logits[(size_t)node * OUT_F + lane] = acc0;
    if (lane < 8) logits[(size_t)node * OUT_F + lane + 32] = acc1;

    float m = fmaxf(acc0, (lane < 8) ? acc1 : -FLT_MAX);
    #pragma unroll
    for (int o = 16; o > 0; o >>= 1) m = fmaxf(m, __shfl_xor_sync(0xffffffffu, m, o));
    float e0 = __expf(acc0 - m);
    float e1 = (lane < 8) ? __expf(acc1 - m) : 0.f;
    float s = e0 + e1;
    #pragma unroll
    for (int o = 16; o > 0; o >>= 1) s += __shfl_xor_sync(0xffffffffu, s, o);
    float inv = 1.f / s;
    soft[(size_t)node * OUT_F + lane] = e0 * inv;
    if (lane < 8) soft[(size_t)node * OUT_F + lane + 32] = e1 * inv;

    int cand = 0x7fffffff;
    if (acc0 == m) cand = lane;
    if (lane < 8 && acc1 == m) cand = min(cand, lane + 32);
    #pragma unroll
    for (int o = 16; o > 0; o >>= 1) cand = min(cand, __shfl_xor_sync(0xffffffffu, cand, o));
    if (lane == 0) hard[node] = (float)cand;
}

extern "C" void kernel_launch(void* const* d_in, const int* in_sizes, int n_in,
                              void* d_out, int out_size) {
    const float* x  = (const float*)d_in[0];
    const void*  ei = d_in[1];
    const float* W1 = (const float*)d_in[2];
    const float* b1 = (const float*)d_in[3];
    const float* W2 = (const float*)d_in[4];
    const float* b2 = (const float*)d_in[5];
    const float* Wc = (const float*)d_in[6];
    const float* bc = (const float*)d_in[7];

    const int N = in_sizes[0] / IN_F;
    const int E = in_sizes[1] / 2;

    float* outp   = (float*)d_out;
    float* logits = outp;
    float* emb    = outp + (size_t)N * OUT_F;
    float* soft   = emb  + (size_t)N * HID;
    float* hard   = soft + (size_t)N * OUT_F;

    const int TB = 256;

    // launch order chosen so GEMM1 is the 4th launch (profiler captures it)
    k_detect<<<1, 32>>>((const long long*)ei, N);                 // 1
    k_deg_init<<<(N + TB - 1) / TB, TB>>>(N);                     // 2
    k_convert<<<(2 * E + TB - 1) / TB, TB>>>(ei, E);              // 3
    k_gemm_hs<IN_F><<<(N + 63) / 64, 256>>>(x, W1, N);            // 4  <- profiled
    k_dinv<<<(N + TB - 1) / TB, TB>>>(N);                         // 5
    k_scan<<<1, 1024>>>(N);                                       // 6
    k_fill<<<(E + TB - 1) / TB, TB>>>(E);                         // 7

    // layer 1 aggregation: g_h1 = relu(agg + b1)
    k_agg<<<((N * 32) + TB - 1) / TB, TB>>>(b1, g_h1, N, 1);      // 8

    // layer 2
    k_gemm_hs<HID><<<(N + 63) / 64, 256>>>(g_h1, W2, N);          // 9
    k_agg<<<((N * 32) + TB - 1) / TB, TB>>>(b2, emb, N, 0);       // 10

    // head
    k_head<<<(N + 7) / 8, 256>>>(emb, Wc, bc, logits, soft, hard, N);  // 11
}

// round 5
// speedup vs baseline: 1.3523x; 1.1406x over previous
#include <cuda_runtime.h>
#include <float.h>

#define N_NODES 100000
#define N_EDGES 1200000
#define IN_F 128
#define HID 64
#define OUT_F 40
#define SCAN_B 1024
#define NSCAN ((N_NODES + SCAN_B - 1) / SCAN_B)   // 98 blocks

// ---------------- device scratch (no allocations allowed) ----------------
__device__ int   g_deg[N_NODES];          // in-degree incl. self-loop
__device__ float g_dinv[N_NODES];
__device__ int   g_rowptr[N_NODES + 1];   // CSR row pointers (real edges only)
__device__ int   g_cur[N_NODES];          // fill cursors
__device__ int   g_csr[N_EDGES];          // src node per CSR slot
__device__ int   g_edge[2 * N_EDGES];     // int32 [src | dst]
__device__ int   g_is64;
__device__ int   g_part[NSCAN];           // per-block partial sums
__device__ int   g_partoff[NSCAN];        // exclusive offsets of partials
__device__ float g_hs[(size_t)N_NODES * HID];    // dinv-prescaled transformed feats
__device__ float g_h1[(size_t)N_NODES * HID];    // layer-1 activations

// -------- init: detect edge dtype + deg=1 (self-loop) --------
__global__ void k_init(const long long* __restrict__ ei, int n) {
    int i = blockIdx.x * blockDim.x + threadIdx.x;
    if (i < n) g_deg[i] = 1;
    if (i == 0) {
        int ok = 1;
        #pragma unroll
        for (int j = 0; j < 16; j++) {
            long long v = ei[j];
            if (v < 0 || v >= n) ok = 0;
        }
        g_is64 = ok;
    }
}

// convert to int32 + count in-degree of dst half in one pass
__global__ void k_convert(const void* __restrict__ ei, int e) {
    int i = blockIdx.x * blockDim.x + threadIdx.x;
    if (i < 2 * e) {
        int v = g_is64 ? (int)((const long long*)ei)[i]
                       : ((const int*)ei)[i];
        g_edge[i] = v;
        if (i >= e) atomicAdd(&g_deg[v], 1);
    }
}

// -------- two-level scan over (deg-1) --------
// A: per-block partial sums (+ dinv computed here so GEMM1 can run next)
__global__ void __launch_bounds__(SCAN_B) k_scanA(int n) {
    __shared__ int wsum[32];
    int t = threadIdx.x, lane = t & 31, wid = t >> 5;
    int i = blockIdx.x * SCAN_B + t;
    int d = (i < n) ? g_deg[i] : 1;
    if (i < n) g_dinv[i] = rsqrtf((float)d);
    int v = d - 1;
    int s = v;
    #pragma unroll
    for (int o = 16; o > 0; o >>= 1) s += __shfl_xor_sync(0xffffffffu, s, o);
    if (lane == 0) wsum[wid] = s;
    __syncthreads();
    if (wid == 0) {
        int ws = wsum[lane];
        #pragma unroll
        for (int o = 16; o > 0; o >>= 1) ws += __shfl_xor_sync(0xffffffffu, ws, o);
        if (lane == 0) g_part[blockIdx.x] = ws;
    }
}

// B: single small block scans the 98 partials
__global__ void k_scanB(int n) {
    __shared__ int sv[128];
    int t = threadIdx.x;  // 128 threads
    int v = (t < NSCAN) ? g_part[t] : 0;
    sv[t] = v;
    __syncthreads();
    #pragma unroll
    for (int o = 1; o < 128; o <<= 1) {
        int add = (t >= o) ? sv[t - o] : 0;
        __syncthreads();
        sv[t] += add;
        __syncthreads();
    }
    if (t < NSCAN) g_partoff[t] = sv[t] - v;       // exclusive
    if (t == NSCAN - 1) g_rowptr[n] = sv[t];       // total real edges
}

// C: local exclusive scan + block offset -> rowptr, cur
__global__ void __launch_bounds__(SCAN_B) k_scanC(int n) {
    __shared__ int wsum[32];
    int t = threadIdx.x, lane = t & 31, wid = t >> 5;
    int i = blockIdx.x * SCAN_B + t;
    int v = (i < n) ? (g_deg[i] - 1) : 0;
    int incl = v;
    #pragma unroll
    for (int o = 1; o < 32; o <<= 1) {
        int u = __shfl_up_sync(0xffffffffu, incl, o);
        if (lane >= o) incl += u;
    }
    if (lane == 31) wsum[wid] = incl;
    __syncthreads();
    if (wid == 0) {
        int ws = wsum[lane];
        int wi = ws;
        #pragma unroll
        for (int o = 1; o < 32; o <<= 1) {
            int u = __shfl_up_sync(0xffffffffu, wi, o);
            if (lane >= o) wi += u;
        }
        wsum[lane] = wi - ws;
    }
    __syncthreads();
    if (i < n) {
        int excl = g_partoff[blockIdx.x] + wsum[wid] + (incl - v);
        g_rowptr[i] = excl;
        g_cur[i] = excl;
    }
}

__global__ void k_fill(int e) {
    int i = blockIdx.x * blockDim.x + threadIdx.x;
    if (i < e) {
        int s = g_edge[i];
        int d = g_edge[e + i];
        int pos = atomicAdd(&g_cur[d], 1);
        g_csr[pos] = s;
    }
}

// --- dense GEMM: g_hs[n,64] = (A[n,K] @ W[K,64]) * dinv[row] (prescaled) ---
// 64x64 tile per 256-thread block, 4x4 register blocking (proven shape).
template <int K>
__global__ void k_gemm_hs(const float* __restrict__ A, const float* __restrict__ W, int n) {
    __shared__ __align__(16) float sW[64 * 64];
    __shared__ float sA[64 * 65];

    const int t = threadIdx.x;           // 256 threads
    const int row0 = blockIdx.x * 64;
    const int ty = t >> 4, tx = t & 15;  // 16x16 thread tile
    const int r0 = ty * 4, c0 = tx * 4;

    float acc[4][4] = {};

    for (int k0 = 0; k0 < K; k0 += 64) {
        __syncthreads();
        for (int i = t; i < 64 * 64 / 4; i += 256)
            ((float4*)sW)[i] = ((const float4*)(W + (size_t)k0 * 64))[i];
        for (int i = t; i < 64 * 16; i += 256) {
            int r = i >> 4;
            int kc = (i & 15) * 4;
            float4 v = make_float4(0.f, 0.f, 0.f, 0.f);
            if (row0 + r < n)
                v = *(const float4*)(A + (size_t)(row0 + r) * K + k0 + kc);
            float* d = &sA[r * 65 + kc];
            d[0] = v.x; d[1] = v.y; d[2] = v.z; d[3] = v.w;
        }
        __syncthreads();

        #pragma unroll 8
        for (int kk = 0; kk < 64; kk++) {
            float4 w4 = *(float4*)&sW[kk * 64 + c0];
            #pragma unroll
            for (int j = 0; j < 4; j++) {
                float a = sA[(r0 + j) * 65 + kk];
                acc[j][0] += a * w4.x;
                acc[j][1] += a * w4.y;
                acc[j][2] += a * w4.z;
                acc[j][3] += a * w4.w;
            }
        }
    }

    #pragma unroll
    for (int j = 0; j < 4; j++) {
        int r = row0 + r0 + j;
        if (r < n) {
            float dv = g_dinv[r];
            *(float4*)&g_hs[(size_t)r * 64 + c0] =
                make_float4(acc[j][0] * dv, acc[j][1] * dv,
                            acc[j][2] * dv, acc[j][3] * dv);
        }
    }
}

// agg: out[v] = act(dinv[v]*(hs[v] + sum_{dst=v} hs[src]) + b)   [hs prescaled]
// one warp per node; lane owns float2; uniform index loads, unroll 4.
__global__ void k_agg(const float* __restrict__ b, float* __restrict__ out,
                      int n, int do_relu) {
    int gw = (blockIdx.x * blockDim.x + threadIdx.x) >> 5;
    int lane = threadIdx.x & 31;
    if (gw >= n) return;

    int beg = g_rowptr[gw], end = g_rowptr[gw + 1];
    float2 a = *(const float2*)(g_hs + (size_t)gw * 64 + 2 * lane);

    int j = beg;
    for (; j + 4 <= end; j += 4) {
        int s0 = g_csr[j];
        int s1 = g_csr[j + 1];
        int s2 = g_csr[j + 2];
        int s3 = g_csr[j + 3];
        float2 v0 = *(const float2*)(g_hs + (size_t)s0 * 64 + 2 * lane);
        float2 v1 = *(const float2*)(g_hs + (size_t)s1 * 64 + 2 * lane);
        float2 v2 = *(const float2*)(g_hs + (size_t)s2 * 64 + 2 * lane);
        float2 v3 = *(const float2*)(g_hs + (size_t)s3 * 64 + 2 * lane);
        a.x += (v0.x + v1.x) + (v2.x + v3.x);
        a.y += (v0.y + v1.y) + (v2.y + v3.y);
    }
    for (; j < end; j++) {
        int s = g_csr[j];
        float2 v = *(const float2*)(g_hs + (size_t)s * 64 + 2 * lane);
        a.x += v.x;
        a.y += v.y;
    }

    float dv = g_dinv[gw];
    float vx = a.x * dv + b[2 * lane];
    float vy = a.y * dv + b[2 * lane + 1];
    if (do_relu) { vx = fmaxf(vx, 0.f); vy = fmaxf(vy, 0.f); }
    *(float2*)(out + (size_t)gw * 64 + 2 * lane) = make_float2(vx, vy);
}

// ------------- head: logits = emb @ Wc + bc, softmax, argmax -------------
// one warp per node, 16 nodes per 512-thread block.
__global__ void __launch_bounds__(512) k_head(const float* __restrict__ emb,
                       const float* __restrict__ Wc,
                       const float* __restrict__ bc, float* __restrict__ logits,
                       float* __restrict__ soft, float* __restrict__ hard, int n) {
    __shared__ float sW[64 * OUT_F];
    __shared__ float sb[OUT_F];
    __shared__ float sE[16][64];

    int t = threadIdx.x;
    for (int i = t; i < 64 * OUT_F; i += 512) sW[i] = Wc[i];
    if (t < OUT_F) sb[t] = bc[t];

    int w = t >> 5, lane = t & 31;
    int node = blockIdx.x * 16 + w;
    if (node < n) {
        sE[w][lane]      = emb[(size_t)node * 64 + lane];
        sE[w][lane + 32] = emb[(size_t)node * 64 + lane + 32];
    }
    __syncthreads();
    if (node >= n) return;

    float acc0 = sb[lane];
    float acc1 = (lane < 8) ? sb[lane + 32] : 0.f;
    #pragma unroll 8
    for (int k = 0; k < 64; k++) {
        float e = sE[w][k];
        acc0 += e * sW[k * OUT_F + lane];
        if (lane < 8) acc1 += e * sW[k * OUT_F + lane + 32];
    }

    logits[(size_t)node * OUT_F + lane] = acc0;
    if (lane < 8) logits[(size_t)node * OUT_F + lane + 32] = acc1;

    float m = fmaxf(acc0, (lane < 8) ? acc1 : -FLT_MAX);
    #pragma unroll
    for (int o = 16; o > 0; o >>= 1) m = fmaxf(m, __shfl_xor_sync(0xffffffffu, m, o));
    float e0 = __expf(acc0 - m);
    float e1 = (lane < 8) ? __expf(acc1 - m) : 0.f;
    float s = e0 + e1;
    #pragma unroll
    for (int o = 16; o > 0; o >>= 1) s += __shfl_xor_sync(0xffffffffu, s, o);
    float inv = 1.f / s;
    soft[(size_t)node * OUT_F + lane] = e0 * inv;
    if (lane < 8) soft[(size_t)node * OUT_F + lane + 32] = e1 * inv;

    int cand = 0x7fffffff;
    if (acc0 == m) cand = lane;
    if (lane < 8 && acc1 == m) cand = min(cand, lane + 32);
    #pragma unroll
    for (int o = 16; o > 0; o >>= 1) cand = min(cand, __shfl_xor_sync(0xffffffffu, cand, o));
    if (lane == 0) hard[node] = (float)cand;
}

extern "C" void kernel_launch(void* const* d_in, const int* in_sizes, int n_in,
                              void* d_out, int out_size) {
    const float* x  = (const float*)d_in[0];
    const void*  ei = d_in[1];
    const float* W1 = (const float*)d_in[2];
    const float* b1 = (const float*)d_in[3];
    const float* W2 = (const float*)d_in[4];
    const float* b2 = (const float*)d_in[5];
    const float* Wc = (const float*)d_in[6];
    const float* bc = (const float*)d_in[7];

    const int N = in_sizes[0] / IN_F;
    const int E = in_sizes[1] / 2;

    float* outp   = (float*)d_out;
    float* logits = outp;
    float* emb    = outp + (size_t)N * OUT_F;
    float* soft   = emb  + (size_t)N * HID;
    float* hard   = soft + (size_t)N * OUT_F;

    const int TB = 256;

    k_init<<<(N + TB - 1) / TB, TB>>>((const long long*)ei, N);   // 1
    k_convert<<<(2 * E + TB - 1) / TB, TB>>>(ei, E);              // 2
    k_scanA<<<NSCAN, SCAN_B>>>(N);                                // 3 (also dinv)
    k_gemm_hs<IN_F><<<(N + 63) / 64, 256>>>(x, W1, N);            // 4  <- profiled
    k_scanB<<<1, 128>>>(N);                                       // 5
    k_scanC<<<NSCAN, SCAN_B>>>(N);                                // 6
    k_fill<<<(E + TB - 1) / TB, TB>>>(E);                         // 7

    // layer 1 aggregation: g_h1 = relu(agg + b1)
    k_agg<<<((N * 32) + TB - 1) / TB, TB>>>(b1, g_h1, N, 1);      // 8

    // layer 2
    k_gemm_hs<HID><<<(N + 63) / 64, 256>>>(g_h1, W2, N);          // 9
    k_agg<<<((N * 32) + TB - 1) / TB, TB>>>(b2, emb, N, 0);       // 10

    // head
    k_head<<<(N + 15) / 16, 512>>>(emb, Wc, bc, logits, soft, hard, N);  // 11
}